// round 14
// baseline (speedup 1.0000x reference)
#include <cuda_runtime.h>
#include <math.h>

#define Bq     16
#define Nn     1024
#define Dd     128
#define VOCABq 32000
#define HOPSq  3
#define HEADSq 4
#define KMAX   128
#define ALPHAq 0.2f
#define ROWS   (Bq * Nn)   // 16384
#define KTOT   512
#define NHOP   (HOPSq + 1)
#define CTAS_PER_B 128     // 1024 rows / 8 rows per CTA

// ---------------- device scratch ----------------
__device__ int   g_nbr_idx[ROWS * KMAX];
__device__ int   g_nbr_cnt[ROWS];
__device__ float g_X4[NHOP * ROWS * Dd];
__device__ float g_wa1[16 * Dd];
__device__ float g_wa2[16 * Dd];
__device__ float g_f1p[NHOP * ROWS * 4];
__device__ float g_f2p[NHOP * ROWS * 4];
__device__ float g_Y[(size_t)ROWS * KTOT];      // 33.5 MB, single hop (only hops 1,2 stored)
__device__ float g_v[Bq * KTOT];
__device__ float g_zcta[2048 * KTOT];           // per-CTA z partials (4 MB)
__device__ float g_z[Bq * KTOT];
__device__ float g_dup2[Bq * 8 * Dd];
__device__ float g_u[Bq * Dd];
__device__ float g_logits[ROWS];
__device__ float g_stats[Bq * 2];               // {max, inv_sum}

// ---------------- neighbor list (float4 + warp scan) ----------------
__global__ void k_build_nbr(const float* __restrict__ adj,
                            const int* __restrict__ kb_len,
                            const int* __restrict__ conv_len) {
    int warp = (blockIdx.x * blockDim.x + threadIdx.x) >> 5;
    int lane = threadIdx.x & 31;
    if (warp >= ROWS) return;
    int b = warp / Nn, n = warp % Nn;
    int ctx = kb_len[b] + conv_len[b];
    const float* arow = adj + (size_t)warp * Nn;
    int* idx = g_nbr_idx + (size_t)warp * KMAX;
    int cnt = 0;
    bool self_ok = (n >= ctx);
    for (int m0 = 0; m0 < Nn; m0 += 128) {
        int mb = m0 + lane * 4;
        float4 a = *(const float4*)(arow + mb);
        bool s0 = (a.x > 0.0f) || (self_ok && mb == n);
        bool s1 = (a.y > 0.0f) || (self_ok && mb + 1 == n);
        bool s2 = (a.z > 0.0f) || (self_ok && mb + 2 == n);
        bool s3 = (a.w > 0.0f) || (self_ok && mb + 3 == n);
        int loc = (int)s0 + (int)s1 + (int)s2 + (int)s3;
        int sc = loc;
#pragma unroll
        for (int o = 1; o < 32; o <<= 1) {
            int t = __shfl_up_sync(0xffffffffu, sc, o);
            if (lane >= o) sc += t;
        }
        int w = cnt + sc - loc;
        if (s0) { if (w < KMAX) idx[w] = mb;     w++; }
        if (s1) { if (w < KMAX) idx[w] = mb + 1; w++; }
        if (s2) { if (w < KMAX) idx[w] = mb + 2; w++; }
        if (s3) { if (w < KMAX) idx[w] = mb + 3; w++; }
        cnt += __shfl_sync(0xffffffffu, sc, 31);
    }
    if (lane == 0) g_nbr_cnt[warp] = cnt < KMAX ? cnt : KMAX;
}

// ---------------- wa = W @ a ----------------
__global__ void k_proj(const float* __restrict__ W_all, const float* __restrict__ a_all) {
    int hh = blockIdx.x;
    int d = threadIdx.x;
    const float* Wrow = W_all + ((size_t)hh * Dd + d) * Dd;
    const float* a = a_all + (size_t)hh * 2 * Dd;
    float s1 = 0.f, s2 = 0.f;
#pragma unroll 4
    for (int e = 0; e < Dd; e++) {
        float w = Wrow[e];
        s1 += w * a[e];
        s2 += w * a[Dd + e];
    }
    g_wa1[hh * Dd + d] = s1;
    g_wa2[hh * Dd + d] = s2;
}

// ---------------- embedding + LM add + fused f1/f2 (all hops) ----------------
__global__ void k_embed_f(const int* __restrict__ story,
                          const int* __restrict__ kb_len,
                          const int* __restrict__ conv_len,
                          const float* __restrict__ dh,
                          const float* __restrict__ emb) {
    int hop = blockIdx.y;
    __shared__ float swa1[HEADSq * Dd];
    __shared__ float swa2[HEADSq * Dd];
    for (int t = threadIdx.x; t < HEADSq * Dd; t += blockDim.x) {
        swa1[t] = g_wa1[hop * HEADSq * Dd + t];
        swa2[t] = g_wa2[hop * HEADSq * Dd + t];
    }
    __syncthreads();
    int warp = (blockIdx.x * blockDim.x + threadIdx.x) >> 5;
    int lane = threadIdx.x & 31;
    if (warp >= ROWS) return;
    int b = warp / Nn, n = warp % Nn;
    const int* st = story + (size_t)warp * 4;
    int i0 = st[0], i1 = st[1], i2 = st[2], i3 = st[3];
    const float* E = emb + (size_t)hop * VOCABq * Dd;
    int d = lane * 4;
    float4 v0 = *(const float4*)(E + (size_t)i0 * Dd + d);
    float4 v1 = *(const float4*)(E + (size_t)i1 * Dd + d);
    float4 v2 = *(const float4*)(E + (size_t)i2 * Dd + d);
    float4 v3 = *(const float4*)(E + (size_t)i3 * Dd + d);
    float4 s;
    s.x = v0.x + v1.x + v2.x + v3.x;
    s.y = v0.y + v1.y + v2.y + v3.y;
    s.z = v0.z + v1.z + v2.z + v3.z;
    s.w = v0.w + v1.w + v2.w + v3.w;
    int rel = n - (kb_len[b] - 1);
    if (rel >= 0 && rel < conv_len[b]) {
        float4 g = *(const float4*)(dh + ((size_t)b * Nn + rel) * Dd + d);
        s.x += g.x; s.y += g.y; s.z += g.z; s.w += g.w;
    }
    *(float4*)(g_X4 + ((size_t)hop * ROWS + warp) * Dd + d) = s;

    float p1[HEADSq], p2[HEADSq];
#pragma unroll
    for (int h = 0; h < HEADSq; h++) {
        const float* w1 = swa1 + h * Dd + d;
        const float* w2 = swa2 + h * Dd + d;
        p1[h] = s.x * w1[0] + s.y * w1[1] + s.z * w1[2] + s.w * w1[3];
        p2[h] = s.x * w2[0] + s.y * w2[1] + s.z * w2[2] + s.w * w2[3];
    }
#pragma unroll
    for (int o = 16; o; o >>= 1)
#pragma unroll
        for (int h = 0; h < HEADSq; h++) {
            p1[h] += __shfl_xor_sync(0xffffffffu, p1[h], o);
            p2[h] += __shfl_xor_sync(0xffffffffu, p2[h], o);
        }
    if (lane == 0) {
        size_t ro = ((size_t)hop * ROWS + warp) * 4;
        *(float4*)(g_f1p + ro) = make_float4(p1[0], p1[1], p1[2], p1[3]);
        *(float4*)(g_f2p + ro) = make_float4(p2[0], p2[1], p2[2], p2[3]);
    }
}

// ---------------- v0 = W[0] @ hidden (standalone, hop 0) ----------------
__global__ void k_vproj(const float* __restrict__ W_all, int hop) {
    int b = blockIdx.x;
    int k = threadIdx.x;
    __shared__ float u_s[Dd];
    if (k < Dd) u_s[k] = g_u[(size_t)b * Dd + k];
    __syncthreads();
    const float4* Wr = (const float4*)(W_all + ((size_t)hop * KTOT + k) * Dd);
    float s = 0.0f;
#pragma unroll 8
    for (int e = 0; e < 32; e++) {
        float4 w = Wr[e];
        float4 uu = *(const float4*)(u_s + e * 4);
        s += w.x * uu.x + w.y * uu.y + w.z * uu.z + w.w * uu.w;
    }
    g_v[(size_t)b * KTOT + k] = s;
}

// ---------------- softmax stats over logits ----------------
__global__ void k_stats() {
    int b = blockIdx.x;
    int tid = threadIdx.x;
    __shared__ float red[256];
    const float* lg = g_logits + (size_t)b * Nn;
    float lmax = -3.4e38f;
    for (int n = tid; n < Nn; n += 256) lmax = fmaxf(lmax, lg[n]);
    red[tid] = lmax; __syncthreads();
    for (int s = 128; s; s >>= 1) { if (tid < s) red[tid] = fmaxf(red[tid], red[tid + s]); __syncthreads(); }
    float mx = red[0]; __syncthreads();
    float lsum = 0.0f;
    for (int n = tid; n < Nn; n += 256) lsum += expf(lg[n] - mx);
    red[tid] = lsum; __syncthreads();
    for (int s = 128; s; s >>= 1) { if (tid < s) red[tid] += red[tid + s]; __syncthreads(); }
    if (tid == 0) { g_stats[b * 2] = mx; g_stats[b * 2 + 1] = 1.0f / red[0]; }
}

// ------ attention: X -> Y row (regs); optional logits0, z-partials, Y store ------
__global__ void k_attn_agg(int hop, int do_z, int store_y) {
    __shared__ float sw[8][HEADSq][KMAX];    // 16 KB
    __shared__ float v_s[KTOT];              // hop 0 only
    __shared__ float zp[8][KTOT];            // 16 KB, do_z only
    int tid = threadIdx.x;
    int wl = tid >> 5;
    int warp = blockIdx.x * 8 + wl;
    int lane = tid & 31;
    int b_blk = (blockIdx.x * 8) / Nn;
    if (hop == 0) {
        for (int t = tid; t < KTOT; t += blockDim.x)
            v_s[t] = g_v[(size_t)b_blk * KTOT + t];
        __syncthreads();
    }
    int b = warp / Nn;
    int cnt = g_nbr_cnt[warp];
    const int* idx = g_nbr_idx + (size_t)warp * KMAX;
    int d = lane * 4;
    const float* X = g_X4 + (size_t)hop * ROWS * Dd;
    const float* F2 = g_f2p + (size_t)hop * ROWS * 4 + (size_t)b * Nn * 4;
    float4 acc[HEADSq];
#pragma unroll
    for (int h = 0; h < HEADSq; h++) acc[h] = make_float4(0.f, 0.f, 0.f, 0.f);

    if (cnt == 0) {
        float4 a = make_float4(0.f, 0.f, 0.f, 0.f);
        for (int m = 0; m < Nn; m++) {
            float4 v = *(const float4*)(X + ((size_t)b * Nn + m) * Dd + d);
            a.x += v.x; a.y += v.y; a.z += v.z; a.w += v.w;
        }
        float sc = 1.0f / (float)Nn;
        a.x *= sc; a.y *= sc; a.z *= sc; a.w *= sc;
#pragma unroll
        for (int h = 0; h < HEADSq; h++) acc[h] = a;
    } else {
        float4 f1v = *(const float4*)(g_f1p + ((size_t)hop * ROWS + warp) * 4);
        float f1h[HEADSq] = {f1v.x, f1v.y, f1v.z, f1v.w};
        float mx[HEADSq];
#pragma unroll
        for (int h = 0; h < HEADSq; h++) mx[h] = -3.4e38f;
        for (int j = lane; j < cnt; j += 32) {
            int m = idx[j];
            float4 f2v = *(const float4*)(F2 + (size_t)m * 4);
            float vv[HEADSq] = {f1h[0] + f2v.x, f1h[1] + f2v.y,
                                f1h[2] + f2v.z, f1h[3] + f2v.w};
#pragma unroll
            for (int h = 0; h < HEADSq; h++) {
                float v = vv[h];
                v = (v >= 0.0f) ? v : ALPHAq * v;
                sw[wl][h][j] = v;
                mx[h] = fmaxf(mx[h], v);
            }
        }
#pragma unroll
        for (int o = 16; o; o >>= 1)
#pragma unroll
            for (int h = 0; h < HEADSq; h++)
                mx[h] = fmaxf(mx[h], __shfl_xor_sync(0xffffffffu, mx[h], o));
        __syncwarp();
        float sum[HEADSq] = {0.f, 0.f, 0.f, 0.f};
        for (int j = lane; j < cnt; j += 32) {
#pragma unroll
            for (int h = 0; h < HEADSq; h++) {
                float w = expf(sw[wl][h][j] - mx[h]);
                sw[wl][h][j] = w;
                sum[h] += w;
            }
        }
#pragma unroll
        for (int o = 16; o; o >>= 1)
#pragma unroll
            for (int h = 0; h < HEADSq; h++)
                sum[h] += __shfl_xor_sync(0xffffffffu, sum[h], o);
        float sc[HEADSq];
#pragma unroll
        for (int h = 0; h < HEADSq; h++) sc[h] = 1.0f / sum[h];
        __syncwarp();

        int j = 0;
        for (; j + 4 <= cnt; j += 4) {
            int m0 = idx[j], m1 = idx[j + 1], m2 = idx[j + 2], m3 = idx[j + 3];
            float4 x0 = *(const float4*)(X + ((size_t)b * Nn + m0) * Dd + d);
            float4 x1 = *(const float4*)(X + ((size_t)b * Nn + m1) * Dd + d);
            float4 x2 = *(const float4*)(X + ((size_t)b * Nn + m2) * Dd + d);
            float4 x3 = *(const float4*)(X + ((size_t)b * Nn + m3) * Dd + d);
#pragma unroll
            for (int h = 0; h < HEADSq; h++) {
                float w0 = sw[wl][h][j]     * sc[h];
                float w1 = sw[wl][h][j + 1] * sc[h];
                float w2 = sw[wl][h][j + 2] * sc[h];
                float w3 = sw[wl][h][j + 3] * sc[h];
                acc[h].x += w0 * x0.x + w1 * x1.x + w2 * x2.x + w3 * x3.x;
                acc[h].y += w0 * x0.y + w1 * x1.y + w2 * x2.y + w3 * x3.y;
                acc[h].z += w0 * x0.z + w1 * x1.z + w2 * x2.z + w3 * x3.z;
                acc[h].w += w0 * x0.w + w1 * x1.w + w2 * x2.w + w3 * x3.w;
            }
        }
        for (; j < cnt; j++) {
            int m = idx[j];
            float4 xv = *(const float4*)(X + ((size_t)b * Nn + m) * Dd + d);
#pragma unroll
            for (int h = 0; h < HEADSq; h++) {
                float w = sw[wl][h][j] * sc[h];
                acc[h].x += w * xv.x; acc[h].y += w * xv.y;
                acc[h].z += w * xv.z; acc[h].w += w * xv.w;
            }
        }
    }

    if (store_y) {
        size_t base = (size_t)warp * KTOT;
#pragma unroll
        for (int h = 0; h < HEADSq; h++)
            *(float4*)(g_Y + base + h * Dd + d) = acc[h];
    }

    if (hop == 0) {
        float lp = 0.0f;
#pragma unroll
        for (int h = 0; h < HEADSq; h++) {
            const float* vp = v_s + h * Dd + d;
            lp += acc[h].x * vp[0] + acc[h].y * vp[1] +
                  acc[h].z * vp[2] + acc[h].w * vp[3];
        }
#pragma unroll
        for (int o = 16; o; o >>= 1) lp += __shfl_xor_sync(0xffffffffu, lp, o);
        if (lane == 0) g_logits[warp] = 0.25f * lp;
    }

    if (do_z) {
        // z partial: p_row * Y_row, reduced over the CTA's 8 rows
        float mxs = g_stats[b_blk * 2], inv = g_stats[b_blk * 2 + 1];
        float p = expf(g_logits[warp] - mxs) * inv;
#pragma unroll
        for (int h = 0; h < HEADSq; h++)
            *(float4*)(&zp[wl][h * Dd + d]) =
                make_float4(p * acc[h].x, p * acc[h].y, p * acc[h].z, p * acc[h].w);
        __syncthreads();
#pragma unroll
        for (int rep = 0; rep < 2; rep++) {
            int c = tid + rep * 256;
            float s = 0.0f;
#pragma unroll
            for (int w = 0; w < 8; w++) s += zp[w][c];
            g_zcta[(size_t)blockIdx.x * KTOT + c] = s;
        }
    }
}

// ---------------- z[b] = sum of 128 CTA partials ----------------
__global__ void k_zred() {
    int b = blockIdx.x, c = threadIdx.x;          // 512 threads
    const float* zc = g_zcta + (size_t)b * CTAS_PER_B * KTOT + c;
    float s = 0.0f;
#pragma unroll 4
    for (int i = 0; i < CTAS_PER_B; i++) s += zc[(size_t)i * KTOT];
    g_z[(size_t)b * KTOT + c] = s;
}

// ---------------- du partials: grid (Bq, 8), 128 thr ----------------
__global__ void k_du2(const float* __restrict__ W_all, int hop) {
    __shared__ float z_s[64];
    int b = blockIdx.x, c = blockIdx.y, tid = threadIdx.x;
    if (tid < 64) z_s[tid] = g_z[(size_t)b * KTOT + c * 64 + tid];
    __syncthreads();
    const float* Wn = W_all + ((size_t)(hop + 1) * KTOT + (size_t)c * 64) * Dd;
    float du = 0.0f;
#pragma unroll 8
    for (int k = 0; k < 64; k++) du += z_s[k] * Wn[(size_t)k * Dd + tid];
    g_dup2[((size_t)b * 8 + c) * Dd + tid] = du;
}

// ---------------- fused: u += 0.25*du; optionally v = W[hop] @ u ----------------
__global__ void k_update(const float* __restrict__ W_all, int hop, int do_v) {
    __shared__ float u_s[Dd];
    int b = blockIdx.x, tid = threadIdx.x;        // 512 threads
    if (tid < Dd) {
        float s = 0.0f;
#pragma unroll
        for (int c = 0; c < 8; c++) s += g_dup2[((size_t)b * 8 + c) * Dd + tid];
        float nu = g_u[(size_t)b * Dd + tid] + 0.25f * s;
        g_u[(size_t)b * Dd + tid] = nu;
        u_s[tid] = nu;
    }
    __syncthreads();
    if (do_v) {
        const float4* Wr = (const float4*)(W_all + ((size_t)hop * KTOT + tid) * Dd);
        float s = 0.0f;
#pragma unroll 8
        for (int e = 0; e < 32; e++) {
            float4 w = Wr[e];
            float4 uu = *(const float4*)(u_s + e * 4);
            s += w.x * uu.x + w.y * uu.y + w.z * uu.z + w.w * uu.w;
        }
        g_v[(size_t)b * KTOT + tid] = s;
    }
}

// ---------------- logits[row] = 0.25 * Y[row] . v_b ----------------
__global__ void k_logits2() {
    __shared__ float v_s[KTOT];
    int wl = threadIdx.x >> 5;
    int lane = threadIdx.x & 31;
    int row = blockIdx.x * 8 + wl;
    int b = (blockIdx.x * 8) / Nn;
    for (int t = threadIdx.x; t < KTOT; t += blockDim.x)
        v_s[t] = g_v[(size_t)b * KTOT + t];
    __syncthreads();
    const float* Yr = g_Y + (size_t)row * KTOT;
    float s = 0.0f;
#pragma unroll
    for (int q = 0; q < 4; q++) {
        int o = q * Dd + lane * 4;
        float4 y = *(const float4*)(Yr + o);
        float4 v = *(const float4*)(v_s + o);
        s += y.x * v.x + y.y * v.y + y.z * v.z + y.w * v.w;
    }
#pragma unroll
    for (int o = 16; o; o >>= 1) s += __shfl_xor_sync(0xffffffffu, s, o);
    if (lane == 0) g_logits[row] = 0.25f * s;
}

// ---------------- init / outputs ----------------
__global__ void k_init_u(const float* __restrict__ hidden) {
    int i = blockIdx.x * blockDim.x + threadIdx.x;
    if (i < Bq * Dd) g_u[i] = hidden[i];
}

__global__ void k_final(float* __restrict__ out) {
    int i = blockIdx.x * blockDim.x + threadIdx.x;
    if (i < ROWS) {
        float l = g_logits[i];
        out[i] = 1.0f / (1.0f + expf(-l));
        out[ROWS + Bq * Dd + i] = l;
    }
    if (i < Bq * Dd) out[ROWS + i] = g_u[i];
}

// ---------------- launch ----------------
extern "C" void kernel_launch(void* const* d_in, const int* in_sizes, int n_in,
                              void* d_out, int out_size) {
    const int*   story  = (const int*)d_in[0];
    const int*   kb     = (const int*)d_in[1];
    const int*   cv     = (const int*)d_in[2];
    const float* hidden = (const float*)d_in[3];
    const float* dh     = (const float*)d_in[4];
    const float* adj    = (const float*)d_in[5];
    const float* emb    = (const float*)d_in[6];
    const float* W      = (const float*)d_in[7];
    const float* a      = (const float*)d_in[8];
    float* out = (float*)d_out;

    k_build_nbr<<<2048, 256>>>(adj, kb, cv);
    k_init_u<<<8, 256>>>(hidden);
    k_proj<<<16, 128>>>(W, a);
    k_embed_f<<<dim3(2048, NHOP), 256>>>(story, kb, cv, dh, emb);

    k_vproj<<<Bq, 512>>>(W, 0);
    k_attn_agg<<<2048, 256>>>(0, 0, 0);          // logits0 fused, no Y store
    k_stats<<<Bq, 256>>>();

    for (int hop = 1; hop < NHOP; hop++) {
        int store_y = (hop < HOPSq) ? 1 : 0;     // Y read only by logits2 (hops 1,2)
        k_attn_agg<<<2048, 256>>>(hop, 1, store_y);
        k_zred<<<Bq, 512>>>();
        k_du2<<<dim3(Bq, 8), 128>>>(W, hop - 1); // uses W[hop]
        k_update<<<Bq, 512>>>(W, hop, store_y);  // u += 0.25 z W[hop]; v = W[hop]@u
        if (store_y) {
            k_logits2<<<2048, 256>>>();
            k_stats<<<Bq, 256>>>();
        }
    }
    k_final<<<(ROWS + 255) / 256, 256>>>(out);
}

// round 15
// speedup vs baseline: 1.1214x; 1.1214x over previous
#include <cuda_runtime.h>
#include <math.h>

#define Bq     16
#define Nn     1024
#define Dd     128
#define VOCABq 32000
#define HOPSq  3
#define HEADSq 4
#define KMAX   128
#define ALPHAq 0.2f
#define ROWS   (Bq * Nn)   // 16384
#define KTOT   512
#define NHOP   (HOPSq + 1)

// ---------------- device scratch ----------------
__device__ int   g_nbr_idx[ROWS * KMAX];
__device__ int   g_nbr_cnt[ROWS];
__device__ float g_X4[NHOP * ROWS * Dd];
__device__ float g_wa1[16 * Dd];
__device__ float g_wa2[16 * Dd];
__device__ float g_f1p[NHOP * ROWS * 4];
__device__ float g_f2p[NHOP * ROWS * 4];
__device__ float g_Y[(size_t)ROWS * KTOT];      // 33.5 MB, ONE hop at a time
__device__ float g_v[Bq * KTOT];
__device__ float g_zpart[Bq * 8 * KTOT];
__device__ float g_dup2[Bq * 8 * Dd];
__device__ float g_u[Bq * Dd];
__device__ float g_logits[ROWS];

// ---------------- neighbor list (float4 + warp scan) ----------------
__global__ void k_build_nbr(const float* __restrict__ adj,
                            const int* __restrict__ kb_len,
                            const int* __restrict__ conv_len) {
    int warp = (blockIdx.x * blockDim.x + threadIdx.x) >> 5;
    int lane = threadIdx.x & 31;
    if (warp >= ROWS) return;
    int b = warp / Nn, n = warp % Nn;
    int ctx = kb_len[b] + conv_len[b];
    const float* arow = adj + (size_t)warp * Nn;
    int* idx = g_nbr_idx + (size_t)warp * KMAX;
    int cnt = 0;
    bool self_ok = (n >= ctx);
    for (int m0 = 0; m0 < Nn; m0 += 128) {
        int mb = m0 + lane * 4;
        float4 a = *(const float4*)(arow + mb);
        bool s0 = (a.x > 0.0f) || (self_ok && mb == n);
        bool s1 = (a.y > 0.0f) || (self_ok && mb + 1 == n);
        bool s2 = (a.z > 0.0f) || (self_ok && mb + 2 == n);
        bool s3 = (a.w > 0.0f) || (self_ok && mb + 3 == n);
        int loc = (int)s0 + (int)s1 + (int)s2 + (int)s3;
        int sc = loc;
#pragma unroll
        for (int o = 1; o < 32; o <<= 1) {
            int t = __shfl_up_sync(0xffffffffu, sc, o);
            if (lane >= o) sc += t;
        }
        int w = cnt + sc - loc;
        if (s0) { if (w < KMAX) idx[w] = mb;     w++; }
        if (s1) { if (w < KMAX) idx[w] = mb + 1; w++; }
        if (s2) { if (w < KMAX) idx[w] = mb + 2; w++; }
        if (s3) { if (w < KMAX) idx[w] = mb + 3; w++; }
        cnt += __shfl_sync(0xffffffffu, sc, 31);
    }
    if (lane == 0) g_nbr_cnt[warp] = cnt < KMAX ? cnt : KMAX;
}

// ---------------- wa = W @ a ----------------
__global__ void k_proj(const float* __restrict__ W_all, const float* __restrict__ a_all) {
    int hh = blockIdx.x;
    int d = threadIdx.x;
    const float* Wrow = W_all + ((size_t)hh * Dd + d) * Dd;
    const float* a = a_all + (size_t)hh * 2 * Dd;
    float s1 = 0.f, s2 = 0.f;
#pragma unroll 4
    for (int e = 0; e < Dd; e++) {
        float w = Wrow[e];
        s1 += w * a[e];
        s2 += w * a[Dd + e];
    }
    g_wa1[hh * Dd + d] = s1;
    g_wa2[hh * Dd + d] = s2;
}

// ---------------- embedding + LM add + fused f1/f2 (all hops) ----------------
__global__ void k_embed_f(const int* __restrict__ story,
                          const int* __restrict__ kb_len,
                          const int* __restrict__ conv_len,
                          const float* __restrict__ dh,
                          const float* __restrict__ emb) {
    int hop = blockIdx.y;
    __shared__ float swa1[HEADSq * Dd];
    __shared__ float swa2[HEADSq * Dd];
    for (int t = threadIdx.x; t < HEADSq * Dd; t += blockDim.x) {
        swa1[t] = g_wa1[hop * HEADSq * Dd + t];
        swa2[t] = g_wa2[hop * HEADSq * Dd + t];
    }
    __syncthreads();
    int warp = (blockIdx.x * blockDim.x + threadIdx.x) >> 5;
    int lane = threadIdx.x & 31;
    if (warp >= ROWS) return;
    int b = warp / Nn, n = warp % Nn;
    const int* st = story + (size_t)warp * 4;
    int i0 = st[0], i1 = st[1], i2 = st[2], i3 = st[3];
    const float* E = emb + (size_t)hop * VOCABq * Dd;
    int d = lane * 4;
    float4 v0 = *(const float4*)(E + (size_t)i0 * Dd + d);
    float4 v1 = *(const float4*)(E + (size_t)i1 * Dd + d);
    float4 v2 = *(const float4*)(E + (size_t)i2 * Dd + d);
    float4 v3 = *(const float4*)(E + (size_t)i3 * Dd + d);
    float4 s;
    s.x = v0.x + v1.x + v2.x + v3.x;
    s.y = v0.y + v1.y + v2.y + v3.y;
    s.z = v0.z + v1.z + v2.z + v3.z;
    s.w = v0.w + v1.w + v2.w + v3.w;
    int rel = n - (kb_len[b] - 1);
    if (rel >= 0 && rel < conv_len[b]) {
        float4 g = *(const float4*)(dh + ((size_t)b * Nn + rel) * Dd + d);
        s.x += g.x; s.y += g.y; s.z += g.z; s.w += g.w;
    }
    *(float4*)(g_X4 + ((size_t)hop * ROWS + warp) * Dd + d) = s;

    float p1[HEADSq], p2[HEADSq];
#pragma unroll
    for (int h = 0; h < HEADSq; h++) {
        const float* w1 = swa1 + h * Dd + d;
        const float* w2 = swa2 + h * Dd + d;
        p1[h] = s.x * w1[0] + s.y * w1[1] + s.z * w1[2] + s.w * w1[3];
        p2[h] = s.x * w2[0] + s.y * w2[1] + s.z * w2[2] + s.w * w2[3];
    }
#pragma unroll
    for (int o = 16; o; o >>= 1)
#pragma unroll
        for (int h = 0; h < HEADSq; h++) {
            p1[h] += __shfl_xor_sync(0xffffffffu, p1[h], o);
            p2[h] += __shfl_xor_sync(0xffffffffu, p2[h], o);
        }
    if (lane == 0) {
        size_t ro = ((size_t)hop * ROWS + warp) * 4;
        *(float4*)(g_f1p + ro) = make_float4(p1[0], p1[1], p1[2], p1[3]);
        *(float4*)(g_f2p + ro) = make_float4(p2[0], p2[1], p2[2], p2[3]);
    }
}

// ---------------- v0 = W[0] @ hidden ----------------
__global__ void k_vproj(const float* __restrict__ W_all, int hop) {
    int b = blockIdx.x;
    int k = threadIdx.x;
    __shared__ float u_s[Dd];
    if (k < Dd) u_s[k] = g_u[(size_t)b * Dd + k];
    __syncthreads();
    const float4* Wr = (const float4*)(W_all + ((size_t)hop * KTOT + k) * Dd);
    float s = 0.0f;
#pragma unroll 8
    for (int e = 0; e < 32; e++) {
        float4 w = Wr[e];
        float4 uu = *(const float4*)(u_s + e * 4);
        s += w.x * uu.x + w.y * uu.y + w.z * uu.z + w.w * uu.w;
    }
    g_v[(size_t)b * KTOT + k] = s;
}

// ------ sparse GAT attention (per hop): aggregate X -> fp32 Y;
//        hop 0 emits logits0, skips Y store (dead) ------
__global__ void k_attn_agg(int hop, int store_y) {
    __shared__ float sw[8][HEADSq][KMAX];
    __shared__ float v_s[KTOT];
    int wl = threadIdx.x >> 5;
    int warp = blockIdx.x * 8 + wl;
    int lane = threadIdx.x & 31;
    int b_blk = (blockIdx.x * 8) / Nn;
    if (hop == 0) {
        for (int t = threadIdx.x; t < KTOT; t += blockDim.x)
            v_s[t] = g_v[(size_t)b_blk * KTOT + t];
        __syncthreads();
    }
    if (warp >= ROWS) return;
    int b = warp / Nn;
    int cnt = g_nbr_cnt[warp];
    const int* idx = g_nbr_idx + (size_t)warp * KMAX;
    int d = lane * 4;
    const float* X = g_X4 + (size_t)hop * ROWS * Dd;
    const float* F2 = g_f2p + (size_t)hop * ROWS * 4 + (size_t)b * Nn * 4;
    float4 acc[HEADSq];
#pragma unroll
    for (int h = 0; h < HEADSq; h++) acc[h] = make_float4(0.f, 0.f, 0.f, 0.f);

    if (cnt == 0) {
        float4 a = make_float4(0.f, 0.f, 0.f, 0.f);
        for (int m = 0; m < Nn; m++) {
            float4 v = *(const float4*)(X + ((size_t)b * Nn + m) * Dd + d);
            a.x += v.x; a.y += v.y; a.z += v.z; a.w += v.w;
        }
        float sc = 1.0f / (float)Nn;
        a.x *= sc; a.y *= sc; a.z *= sc; a.w *= sc;
#pragma unroll
        for (int h = 0; h < HEADSq; h++) acc[h] = a;
    } else {
        float4 f1v = *(const float4*)(g_f1p + ((size_t)hop * ROWS + warp) * 4);
        float f1h[HEADSq] = {f1v.x, f1v.y, f1v.z, f1v.w};
        float mx[HEADSq];
#pragma unroll
        for (int h = 0; h < HEADSq; h++) mx[h] = -3.4e38f;
        for (int j = lane; j < cnt; j += 32) {
            int m = idx[j];
            float4 f2v = *(const float4*)(F2 + (size_t)m * 4);
            float vv[HEADSq] = {f1h[0] + f2v.x, f1h[1] + f2v.y,
                                f1h[2] + f2v.z, f1h[3] + f2v.w};
#pragma unroll
            for (int h = 0; h < HEADSq; h++) {
                float v = vv[h];
                v = (v >= 0.0f) ? v : ALPHAq * v;
                sw[wl][h][j] = v;
                mx[h] = fmaxf(mx[h], v);
            }
        }
#pragma unroll
        for (int o = 16; o; o >>= 1)
#pragma unroll
            for (int h = 0; h < HEADSq; h++)
                mx[h] = fmaxf(mx[h], __shfl_xor_sync(0xffffffffu, mx[h], o));
        __syncwarp();
        float sum[HEADSq] = {0.f, 0.f, 0.f, 0.f};
        for (int j = lane; j < cnt; j += 32) {
#pragma unroll
            for (int h = 0; h < HEADSq; h++) {
                float w = expf(sw[wl][h][j] - mx[h]);
                sw[wl][h][j] = w;
                sum[h] += w;
            }
        }
#pragma unroll
        for (int o = 16; o; o >>= 1)
#pragma unroll
            for (int h = 0; h < HEADSq; h++)
                sum[h] += __shfl_xor_sync(0xffffffffu, sum[h], o);
        float sc[HEADSq];
#pragma unroll
        for (int h = 0; h < HEADSq; h++) sc[h] = 1.0f / sum[h];
        __syncwarp();

        int j = 0;
        for (; j + 4 <= cnt; j += 4) {
            int m0 = idx[j], m1 = idx[j + 1], m2 = idx[j + 2], m3 = idx[j + 3];
            float4 x0 = *(const float4*)(X + ((size_t)b * Nn + m0) * Dd + d);
            float4 x1 = *(const float4*)(X + ((size_t)b * Nn + m1) * Dd + d);
            float4 x2 = *(const float4*)(X + ((size_t)b * Nn + m2) * Dd + d);
            float4 x3 = *(const float4*)(X + ((size_t)b * Nn + m3) * Dd + d);
#pragma unroll
            for (int h = 0; h < HEADSq; h++) {
                float w0 = sw[wl][h][j]     * sc[h];
                float w1 = sw[wl][h][j + 1] * sc[h];
                float w2 = sw[wl][h][j + 2] * sc[h];
                float w3 = sw[wl][h][j + 3] * sc[h];
                acc[h].x += w0 * x0.x + w1 * x1.x + w2 * x2.x + w3 * x3.x;
                acc[h].y += w0 * x0.y + w1 * x1.y + w2 * x2.y + w3 * x3.y;
                acc[h].z += w0 * x0.z + w1 * x1.z + w2 * x2.z + w3 * x3.z;
                acc[h].w += w0 * x0.w + w1 * x1.w + w2 * x2.w + w3 * x3.w;
            }
        }
        for (; j < cnt; j++) {
            int m = idx[j];
            float4 xv = *(const float4*)(X + ((size_t)b * Nn + m) * Dd + d);
#pragma unroll
            for (int h = 0; h < HEADSq; h++) {
                float w = sw[wl][h][j] * sc[h];
                acc[h].x += w * xv.x; acc[h].y += w * xv.y;
                acc[h].z += w * xv.z; acc[h].w += w * xv.w;
            }
        }
    }

    if (store_y) {
        size_t base = (size_t)warp * KTOT;
#pragma unroll
        for (int h = 0; h < HEADSq; h++)
            *(float4*)(g_Y + base + h * Dd + d) = acc[h];
    }

    if (hop == 0) {
        float lp = 0.0f;
#pragma unroll
        for (int h = 0; h < HEADSq; h++) {
            const float* vp = v_s + h * Dd + d;
            lp += acc[h].x * vp[0] + acc[h].y * vp[1] +
                  acc[h].z * vp[2] + acc[h].w * vp[3];
        }
#pragma unroll
        for (int o = 16; o; o >>= 1) lp += __shfl_xor_sync(0xffffffffu, lp, o);
        if (lane == 0) g_logits[warp] = 0.25f * lp;
    }
}

// ---------------- logits[row] = 0.25 * Y[row] . v_b ----------------
__global__ void k_logits2() {
    __shared__ float v_s[KTOT];
    int wl = threadIdx.x >> 5;
    int lane = threadIdx.x & 31;
    int row = blockIdx.x * 8 + wl;
    int b = (blockIdx.x * 8) / Nn;
    for (int t = threadIdx.x; t < KTOT; t += blockDim.x)
        v_s[t] = g_v[(size_t)b * KTOT + t];
    __syncthreads();
    const float* Yr = g_Y + (size_t)row * KTOT;
    float s = 0.0f;
#pragma unroll
    for (int q = 0; q < 4; q++) {
        int o = q * Dd + lane * 4;
        float4 y = *(const float4*)(Yr + o);
        float4 v = *(const float4*)(v_s + o);
        s += y.x * v.x + y.y * v.y + y.z * v.z + y.w * v.w;
    }
#pragma unroll
    for (int o = 16; o; o >>= 1) s += __shfl_xor_sync(0xffffffffu, s, o);
    if (lane == 0) g_logits[row] = 0.25f * s;
}

// ---------------- z partials: z_b = softmax(logits_b) . Y[b] (stats inline) ----------------
__global__ void k_zpass() {
    __shared__ float red[256];
    __shared__ float zw[8][KTOT];
    int b = blockIdx.x, split = blockIdx.y;
    int tid = threadIdx.x, wl = tid >> 5, lane = tid & 31;
    const float* lg = g_logits + (size_t)b * Nn;

    float m = -3.4e38f;
#pragma unroll
    for (int i = 0; i < 4; i++) m = fmaxf(m, lg[tid + i * 256]);
    red[tid] = m; __syncthreads();
    for (int s = 128; s; s >>= 1) { if (tid < s) red[tid] = fmaxf(red[tid], red[tid + s]); __syncthreads(); }
    float mx = red[0]; __syncthreads();
    float sum = 0.0f;
#pragma unroll
    for (int i = 0; i < 4; i++) sum += expf(lg[tid + i * 256] - mx);
    red[tid] = sum; __syncthreads();
    for (int s = 128; s; s >>= 1) { if (tid < s) red[tid] += red[tid + s]; __syncthreads(); }
    float inv = 1.0f / red[0];
    __syncthreads();

    float zr[16];
#pragma unroll
    for (int i = 0; i < 16; i++) zr[i] = 0.0f;
    int r0 = split * 128 + wl * 16;
    const float* Yb = g_Y + (size_t)b * Nn * KTOT;
    for (int i = 0; i < 16; i++) {
        int r = r0 + i;
        float p = expf(lg[r] - mx);
        const float* Yr = Yb + (size_t)r * KTOT;
#pragma unroll
        for (int q = 0; q < 4; q++) {
            float4 y = *(const float4*)(Yr + q * Dd + lane * 4);
            zr[q * 4 + 0] += p * y.x;
            zr[q * 4 + 1] += p * y.y;
            zr[q * 4 + 2] += p * y.z;
            zr[q * 4 + 3] += p * y.w;
        }
    }
#pragma unroll
    for (int q = 0; q < 4; q++)
        *(float4*)(&zw[wl][q * Dd + lane * 4]) =
            make_float4(zr[q * 4], zr[q * 4 + 1], zr[q * 4 + 2], zr[q * 4 + 3]);
    __syncthreads();
#pragma unroll
    for (int rep = 0; rep < 2; rep++) {
        int c = tid + rep * 256;
        float s = 0.0f;
#pragma unroll
        for (int w = 0; w < 8; w++) s += zw[w][c];
        g_zpart[((size_t)b * 8 + split) * KTOT + c] = s * inv;
    }
}

// ---------------- du partials: grid (Bq, 8), 128 thr ----------------
__global__ void k_du2(const float* __restrict__ W_all, int hop) {
    __shared__ float z_s[64];
    int b = blockIdx.x, c = blockIdx.y, tid = threadIdx.x;
    if (tid < 64) {
        int k = c * 64 + tid;
        float s = 0.0f;
#pragma unroll
        for (int s8 = 0; s8 < 8; s8++)
            s += g_zpart[((size_t)b * 8 + s8) * KTOT + k];
        z_s[tid] = s;
    }
    __syncthreads();
    const float* Wn = W_all + ((size_t)(hop + 1) * KTOT + (size_t)c * 64) * Dd;
    float du = 0.0f;
#pragma unroll 8
    for (int k = 0; k < 64; k++) du += z_s[k] * Wn[(size_t)k * Dd + tid];
    g_dup2[((size_t)b * 8 + c) * Dd + tid] = du;
}

// ---------------- fused: u += 0.25*du; optionally v = W[hop] @ u ----------------
__global__ void k_update(const float* __restrict__ W_all, int hop, int do_v) {
    __shared__ float u_s[Dd];
    int b = blockIdx.x, tid = threadIdx.x;        // 512 threads
    if (tid < Dd) {
        float s = 0.0f;
#pragma unroll
        for (int c = 0; c < 8; c++) s += g_dup2[((size_t)b * 8 + c) * Dd + tid];
        float nu = g_u[(size_t)b * Dd + tid] + 0.25f * s;
        g_u[(size_t)b * Dd + tid] = nu;
        u_s[tid] = nu;
    }
    __syncthreads();
    if (do_v) {
        const float4* Wr = (const float4*)(W_all + ((size_t)hop * KTOT + tid) * Dd);
        float s = 0.0f;
#pragma unroll 8
        for (int e = 0; e < 32; e++) {
            float4 w = Wr[e];
            float4 uu = *(const float4*)(u_s + e * 4);
            s += w.x * uu.x + w.y * uu.y + w.z * uu.z + w.w * uu.w;
        }
        g_v[(size_t)b * KTOT + tid] = s;
    }
}

// ---------------- init / outputs ----------------
__global__ void k_init_u(const float* __restrict__ hidden) {
    int i = blockIdx.x * blockDim.x + threadIdx.x;
    if (i < Bq * Dd) g_u[i] = hidden[i];
}

__global__ void k_final(float* __restrict__ out) {
    int i = blockIdx.x * blockDim.x + threadIdx.x;
    if (i < ROWS) {
        float l = g_logits[i];
        out[i] = 1.0f / (1.0f + expf(-l));
        out[ROWS + Bq * Dd + i] = l;
    }
    if (i < Bq * Dd) out[ROWS + i] = g_u[i];
}

// ---------------- launch ----------------
extern "C" void kernel_launch(void* const* d_in, const int* in_sizes, int n_in,
                              void* d_out, int out_size) {
    const int*   story  = (const int*)d_in[0];
    const int*   kb     = (const int*)d_in[1];
    const int*   cv     = (const int*)d_in[2];
    const float* hidden = (const float*)d_in[3];
    const float* dh     = (const float*)d_in[4];
    const float* adj    = (const float*)d_in[5];
    const float* emb    = (const float*)d_in[6];
    const float* W      = (const float*)d_in[7];
    const float* a      = (const float*)d_in[8];
    float* out = (float*)d_out;

    k_build_nbr<<<2048, 256>>>(adj, kb, cv);
    k_init_u<<<8, 256>>>(hidden);
    k_proj<<<16, 128>>>(W, a);
    k_embed_f<<<dim3(2048, NHOP), 256>>>(story, kb, cv, dh, emb);

    k_vproj<<<Bq, 512>>>(W, 0);

    for (int hop = 0; hop < NHOP; hop++) {
        int store_y = (hop >= 1) ? 1 : 0;          // Y(0) is dead (logits0 fused)
        k_attn_agg<<<2048, 256>>>(hop, store_y);
        if (hop >= 1) {
            k_zpass<<<dim3(Bq, 8), 256>>>();       // stats inline, reads Y + logits_{hop-1}
            k_du2<<<dim3(Bq, 8), 128>>>(W, hop - 1);
            int do_v = (hop < HOPSq) ? 1 : 0;
            k_update<<<Bq, 512>>>(W, hop, do_v);   // u += 0.25 z W[hop]; v = W[hop]@u
            if (do_v) k_logits2<<<2048, 256>>>();
        }
    }
    k_final<<<(ROWS + 255) / 256, 256>>>(out);
}

// round 16
// speedup vs baseline: 1.1429x; 1.0192x over previous
#include <cuda_runtime.h>
#include <math.h>

#define Bq     16
#define Nn     1024
#define Dd     128
#define VOCABq 32000
#define HOPSq  3
#define HEADSq 4
#define KMAX   128
#define ALPHAq 0.2f
#define ROWS   (Bq * Nn)   // 16384
#define KTOT   512
#define NHOP   (HOPSq + 1)

// ---------------- device scratch ----------------
__device__ int   g_nbr_idx[ROWS * KMAX];
__device__ int   g_nbr_cnt[ROWS];
__device__ float g_X4[NHOP * ROWS * Dd];
__device__ float g_wa1[16 * Dd];
__device__ float g_wa2[16 * Dd];
__device__ float g_f1p[NHOP * ROWS * 4];
__device__ float g_f2p[NHOP * ROWS * 4];
__device__ float g_Y[(size_t)ROWS * KTOT];      // buffer 0
__device__ float g_Y2[(size_t)ROWS * KTOT];     // buffer 1 (enables overlap)
__device__ float g_v[Bq * KTOT];
__device__ float g_zpart[Bq * 8 * KTOT];
__device__ float g_dup2[Bq * 8 * Dd];
__device__ float g_u[Bq * Dd];
__device__ float g_logits[ROWS];

// ---------------- neighbor list (float4 + warp scan) ----------------
__global__ void k_build_nbr(const float* __restrict__ adj,
                            const int* __restrict__ kb_len,
                            const int* __restrict__ conv_len) {
    int warp = (blockIdx.x * blockDim.x + threadIdx.x) >> 5;
    int lane = threadIdx.x & 31;
    if (warp >= ROWS) return;
    int b = warp / Nn, n = warp % Nn;
    int ctx = kb_len[b] + conv_len[b];
    const float* arow = adj + (size_t)warp * Nn;
    int* idx = g_nbr_idx + (size_t)warp * KMAX;
    int cnt = 0;
    bool self_ok = (n >= ctx);
    for (int m0 = 0; m0 < Nn; m0 += 128) {
        int mb = m0 + lane * 4;
        float4 a = *(const float4*)(arow + mb);
        bool s0 = (a.x > 0.0f) || (self_ok && mb == n);
        bool s1 = (a.y > 0.0f) || (self_ok && mb + 1 == n);
        bool s2 = (a.z > 0.0f) || (self_ok && mb + 2 == n);
        bool s3 = (a.w > 0.0f) || (self_ok && mb + 3 == n);
        int loc = (int)s0 + (int)s1 + (int)s2 + (int)s3;
        int sc = loc;
#pragma unroll
        for (int o = 1; o < 32; o <<= 1) {
            int t = __shfl_up_sync(0xffffffffu, sc, o);
            if (lane >= o) sc += t;
        }
        int w = cnt + sc - loc;
        if (s0) { if (w < KMAX) idx[w] = mb;     w++; }
        if (s1) { if (w < KMAX) idx[w] = mb + 1; w++; }
        if (s2) { if (w < KMAX) idx[w] = mb + 2; w++; }
        if (s3) { if (w < KMAX) idx[w] = mb + 3; w++; }
        cnt += __shfl_sync(0xffffffffu, sc, 31);
    }
    if (lane == 0) g_nbr_cnt[warp] = cnt < KMAX ? cnt : KMAX;
}

// ---------------- wa = W @ a ----------------
__global__ void k_proj(const float* __restrict__ W_all, const float* __restrict__ a_all) {
    int hh = blockIdx.x;
    int d = threadIdx.x;
    const float* Wrow = W_all + ((size_t)hh * Dd + d) * Dd;
    const float* a = a_all + (size_t)hh * 2 * Dd;
    float s1 = 0.f, s2 = 0.f;
#pragma unroll 4
    for (int e = 0; e < Dd; e++) {
        float w = Wrow[e];
        s1 += w * a[e];
        s2 += w * a[Dd + e];
    }
    g_wa1[hh * Dd + d] = s1;
    g_wa2[hh * Dd + d] = s2;
}

// ---------------- embedding + LM add + fused f1/f2 (all hops) ----------------
__global__ void k_embed_f(const int* __restrict__ story,
                          const int* __restrict__ kb_len,
                          const int* __restrict__ conv_len,
                          const float* __restrict__ dh,
                          const float* __restrict__ emb) {
    int hop = blockIdx.y;
    __shared__ float swa1[HEADSq * Dd];
    __shared__ float swa2[HEADSq * Dd];
    for (int t = threadIdx.x; t < HEADSq * Dd; t += blockDim.x) {
        swa1[t] = g_wa1[hop * HEADSq * Dd + t];
        swa2[t] = g_wa2[hop * HEADSq * Dd + t];
    }
    __syncthreads();
    int warp = (blockIdx.x * blockDim.x + threadIdx.x) >> 5;
    int lane = threadIdx.x & 31;
    if (warp >= ROWS) return;
    int b = warp / Nn, n = warp % Nn;
    const int* st = story + (size_t)warp * 4;
    int i0 = st[0], i1 = st[1], i2 = st[2], i3 = st[3];
    const float* E = emb + (size_t)hop * VOCABq * Dd;
    int d = lane * 4;
    float4 v0 = *(const float4*)(E + (size_t)i0 * Dd + d);
    float4 v1 = *(const float4*)(E + (size_t)i1 * Dd + d);
    float4 v2 = *(const float4*)(E + (size_t)i2 * Dd + d);
    float4 v3 = *(const float4*)(E + (size_t)i3 * Dd + d);
    float4 s;
    s.x = v0.x + v1.x + v2.x + v3.x;
    s.y = v0.y + v1.y + v2.y + v3.y;
    s.z = v0.z + v1.z + v2.z + v3.z;
    s.w = v0.w + v1.w + v2.w + v3.w;
    int rel = n - (kb_len[b] - 1);
    if (rel >= 0 && rel < conv_len[b]) {
        float4 g = *(const float4*)(dh + ((size_t)b * Nn + rel) * Dd + d);
        s.x += g.x; s.y += g.y; s.z += g.z; s.w += g.w;
    }
    *(float4*)(g_X4 + ((size_t)hop * ROWS + warp) * Dd + d) = s;

    float p1[HEADSq], p2[HEADSq];
#pragma unroll
    for (int h = 0; h < HEADSq; h++) {
        const float* w1 = swa1 + h * Dd + d;
        const float* w2 = swa2 + h * Dd + d;
        p1[h] = s.x * w1[0] + s.y * w1[1] + s.z * w1[2] + s.w * w1[3];
        p2[h] = s.x * w2[0] + s.y * w2[1] + s.z * w2[2] + s.w * w2[3];
    }
#pragma unroll
    for (int o = 16; o; o >>= 1)
#pragma unroll
        for (int h = 0; h < HEADSq; h++) {
            p1[h] += __shfl_xor_sync(0xffffffffu, p1[h], o);
            p2[h] += __shfl_xor_sync(0xffffffffu, p2[h], o);
        }
    if (lane == 0) {
        size_t ro = ((size_t)hop * ROWS + warp) * 4;
        *(float4*)(g_f1p + ro) = make_float4(p1[0], p1[1], p1[2], p1[3]);
        *(float4*)(g_f2p + ro) = make_float4(p2[0], p2[1], p2[2], p2[3]);
    }
}

// ---------------- v0 = W[0] @ hidden (reads input directly) ----------------
__global__ void k_vproj0(const float* __restrict__ W_all, const float* __restrict__ hidden) {
    int b = blockIdx.x;
    int k = threadIdx.x;
    __shared__ float u_s[Dd];
    if (k < Dd) u_s[k] = hidden[(size_t)b * Dd + k];
    __syncthreads();
    const float4* Wr = (const float4*)(W_all + (size_t)k * Dd);
    float s = 0.0f;
#pragma unroll 8
    for (int e = 0; e < 32; e++) {
        float4 w = Wr[e];
        float4 uu = *(const float4*)(u_s + e * 4);
        s += w.x * uu.x + w.y * uu.y + w.z * uu.z + w.w * uu.w;
    }
    g_v[(size_t)b * KTOT + k] = s;
}

// ------ sparse GAT attention: X -> Y[ybuf]; hop 0 emits logits0, no Y store ------
__global__ void k_attn_agg(int hop, int store_y, int ybuf) {
    __shared__ float sw[8][HEADSq][KMAX];
    __shared__ float v_s[KTOT];
    int wl = threadIdx.x >> 5;
    int warp = blockIdx.x * 8 + wl;
    int lane = threadIdx.x & 31;
    int b_blk = (blockIdx.x * 8) / Nn;
    if (hop == 0) {
        for (int t = threadIdx.x; t < KTOT; t += blockDim.x)
            v_s[t] = g_v[(size_t)b_blk * KTOT + t];
        __syncthreads();
    }
    if (warp >= ROWS) return;
    int b = warp / Nn;
    int cnt = g_nbr_cnt[warp];
    const int* idx = g_nbr_idx + (size_t)warp * KMAX;
    int d = lane * 4;
    const float* X = g_X4 + (size_t)hop * ROWS * Dd;
    const float* F2 = g_f2p + (size_t)hop * ROWS * 4 + (size_t)b * Nn * 4;
    float4 acc[HEADSq];
#pragma unroll
    for (int h = 0; h < HEADSq; h++) acc[h] = make_float4(0.f, 0.f, 0.f, 0.f);

    if (cnt == 0) {
        float4 a = make_float4(0.f, 0.f, 0.f, 0.f);
        for (int m = 0; m < Nn; m++) {
            float4 v = *(const float4*)(X + ((size_t)b * Nn + m) * Dd + d);
            a.x += v.x; a.y += v.y; a.z += v.z; a.w += v.w;
        }
        float sc = 1.0f / (float)Nn;
        a.x *= sc; a.y *= sc; a.z *= sc; a.w *= sc;
#pragma unroll
        for (int h = 0; h < HEADSq; h++) acc[h] = a;
    } else {
        float4 f1v = *(const float4*)(g_f1p + ((size_t)hop * ROWS + warp) * 4);
        float f1h[HEADSq] = {f1v.x, f1v.y, f1v.z, f1v.w};
        float mx[HEADSq];
#pragma unroll
        for (int h = 0; h < HEADSq; h++) mx[h] = -3.4e38f;
        for (int j = lane; j < cnt; j += 32) {
            int m = idx[j];
            float4 f2v = *(const float4*)(F2 + (size_t)m * 4);
            float vv[HEADSq] = {f1h[0] + f2v.x, f1h[1] + f2v.y,
                                f1h[2] + f2v.z, f1h[3] + f2v.w};
#pragma unroll
            for (int h = 0; h < HEADSq; h++) {
                float v = vv[h];
                v = (v >= 0.0f) ? v : ALPHAq * v;
                sw[wl][h][j] = v;
                mx[h] = fmaxf(mx[h], v);
            }
        }
#pragma unroll
        for (int o = 16; o; o >>= 1)
#pragma unroll
            for (int h = 0; h < HEADSq; h++)
                mx[h] = fmaxf(mx[h], __shfl_xor_sync(0xffffffffu, mx[h], o));
        __syncwarp();
        float sum[HEADSq] = {0.f, 0.f, 0.f, 0.f};
        for (int j = lane; j < cnt; j += 32) {
#pragma unroll
            for (int h = 0; h < HEADSq; h++) {
                float w = expf(sw[wl][h][j] - mx[h]);
                sw[wl][h][j] = w;
                sum[h] += w;
            }
        }
#pragma unroll
        for (int o = 16; o; o >>= 1)
#pragma unroll
            for (int h = 0; h < HEADSq; h++)
                sum[h] += __shfl_xor_sync(0xffffffffu, sum[h], o);
        float sc[HEADSq];
#pragma unroll
        for (int h = 0; h < HEADSq; h++) sc[h] = 1.0f / sum[h];
        __syncwarp();

        int j = 0;
        for (; j + 4 <= cnt; j += 4) {
            int m0 = idx[j], m1 = idx[j + 1], m2 = idx[j + 2], m3 = idx[j + 3];
            float4 x0 = *(const float4*)(X + ((size_t)b * Nn + m0) * Dd + d);
            float4 x1 = *(const float4*)(X + ((size_t)b * Nn + m1) * Dd + d);
            float4 x2 = *(const float4*)(X + ((size_t)b * Nn + m2) * Dd + d);
            float4 x3 = *(const float4*)(X + ((size_t)b * Nn + m3) * Dd + d);
#pragma unroll
            for (int h = 0; h < HEADSq; h++) {
                float w0 = sw[wl][h][j]     * sc[h];
                float w1 = sw[wl][h][j + 1] * sc[h];
                float w2 = sw[wl][h][j + 2] * sc[h];
                float w3 = sw[wl][h][j + 3] * sc[h];
                acc[h].x += w0 * x0.x + w1 * x1.x + w2 * x2.x + w3 * x3.x;
                acc[h].y += w0 * x0.y + w1 * x1.y + w2 * x2.y + w3 * x3.y;
                acc[h].z += w0 * x0.z + w1 * x1.z + w2 * x2.z + w3 * x3.z;
                acc[h].w += w0 * x0.w + w1 * x1.w + w2 * x2.w + w3 * x3.w;
            }
        }
        for (; j < cnt; j++) {
            int m = idx[j];
            float4 xv = *(const float4*)(X + ((size_t)b * Nn + m) * Dd + d);
#pragma unroll
            for (int h = 0; h < HEADSq; h++) {
                float w = sw[wl][h][j] * sc[h];
                acc[h].x += w * xv.x; acc[h].y += w * xv.y;
                acc[h].z += w * xv.z; acc[h].w += w * xv.w;
            }
        }
    }

    if (store_y) {
        float* Yb = ybuf ? g_Y2 : g_Y;
        size_t base = (size_t)warp * KTOT;
#pragma unroll
        for (int h = 0; h < HEADSq; h++)
            *(float4*)(Yb + base + h * Dd + d) = acc[h];
    }

    if (hop == 0) {
        float lp = 0.0f;
#pragma unroll
        for (int h = 0; h < HEADSq; h++) {
            const float* vp = v_s + h * Dd + d;
            lp += acc[h].x * vp[0] + acc[h].y * vp[1] +
                  acc[h].z * vp[2] + acc[h].w * vp[3];
        }
#pragma unroll
        for (int o = 16; o; o >>= 1) lp += __shfl_xor_sync(0xffffffffu, lp, o);
        if (lane == 0) g_logits[warp] = 0.25f * lp;
    }
}

// ---------------- logits[row] = 0.25 * Y[row] . v_b ----------------
__global__ void k_logits2(int ybuf) {
    __shared__ float v_s[KTOT];
    int wl = threadIdx.x >> 5;
    int lane = threadIdx.x & 31;
    int row = blockIdx.x * 8 + wl;
    int b = (blockIdx.x * 8) / Nn;
    for (int t = threadIdx.x; t < KTOT; t += blockDim.x)
        v_s[t] = g_v[(size_t)b * KTOT + t];
    __syncthreads();
    const float* Yb = ybuf ? g_Y2 : g_Y;
    const float* Yr = Yb + (size_t)row * KTOT;
    float s = 0.0f;
#pragma unroll
    for (int q = 0; q < 4; q++) {
        int o = q * Dd + lane * 4;
        float4 y = *(const float4*)(Yr + o);
        float4 v = *(const float4*)(v_s + o);
        s += y.x * v.x + y.y * v.y + y.z * v.z + y.w * v.w;
    }
#pragma unroll
    for (int o = 16; o; o >>= 1) s += __shfl_xor_sync(0xffffffffu, s, o);
    if (lane == 0) g_logits[row] = 0.25f * s;
}

// ---------------- z partials: z_b = softmax(logits_b) . Y[b] (stats inline) ----------------
__global__ void k_zpass(int ybuf) {
    __shared__ float red[256];
    __shared__ float zw[8][KTOT];
    int b = blockIdx.x, split = blockIdx.y;
    int tid = threadIdx.x, wl = tid >> 5, lane = tid & 31;
    const float* lg = g_logits + (size_t)b * Nn;

    float m = -3.4e38f;
#pragma unroll
    for (int i = 0; i < 4; i++) m = fmaxf(m, lg[tid + i * 256]);
    red[tid] = m; __syncthreads();
    for (int s = 128; s; s >>= 1) { if (tid < s) red[tid] = fmaxf(red[tid], red[tid + s]); __syncthreads(); }
    float mx = red[0]; __syncthreads();
    float sum = 0.0f;
#pragma unroll
    for (int i = 0; i < 4; i++) sum += expf(lg[tid + i * 256] - mx);
    red[tid] = sum; __syncthreads();
    for (int s = 128; s; s >>= 1) { if (tid < s) red[tid] += red[tid + s]; __syncthreads(); }
    float inv = 1.0f / red[0];
    __syncthreads();

    float zr[16];
#pragma unroll
    for (int i = 0; i < 16; i++) zr[i] = 0.0f;
    int r0 = split * 128 + wl * 16;
    const float* Ybase = (ybuf ? g_Y2 : g_Y) + (size_t)b * Nn * KTOT;
    for (int i = 0; i < 16; i++) {
        int r = r0 + i;
        float p = expf(lg[r] - mx);
        const float* Yr = Ybase + (size_t)r * KTOT;
#pragma unroll
        for (int q = 0; q < 4; q++) {
            float4 y = *(const float4*)(Yr + q * Dd + lane * 4);
            zr[q * 4 + 0] += p * y.x;
            zr[q * 4 + 1] += p * y.y;
            zr[q * 4 + 2] += p * y.z;
            zr[q * 4 + 3] += p * y.w;
        }
    }
#pragma unroll
    for (int q = 0; q < 4; q++)
        *(float4*)(&zw[wl][q * Dd + lane * 4]) =
            make_float4(zr[q * 4], zr[q * 4 + 1], zr[q * 4 + 2], zr[q * 4 + 3]);
    __syncthreads();
#pragma unroll
    for (int rep = 0; rep < 2; rep++) {
        int c = tid + rep * 256;
        float s = 0.0f;
#pragma unroll
        for (int w = 0; w < 8; w++) s += zw[w][c];
        g_zpart[((size_t)b * 8 + split) * KTOT + c] = s * inv;
    }
}

// ---------------- du partials: grid (Bq, 8), 128 thr ----------------
__global__ void k_du2(const float* __restrict__ W_all, int hop) {
    __shared__ float z_s[64];
    int b = blockIdx.x, c = blockIdx.y, tid = threadIdx.x;
    if (tid < 64) {
        int k = c * 64 + tid;
        float s = 0.0f;
#pragma unroll
        for (int s8 = 0; s8 < 8; s8++)
            s += g_zpart[((size_t)b * 8 + s8) * KTOT + k];
        z_s[tid] = s;
    }
    __syncthreads();
    const float* Wn = W_all + ((size_t)(hop + 1) * KTOT + (size_t)c * 64) * Dd;
    float du = 0.0f;
#pragma unroll 8
    for (int k = 0; k < 64; k++) du += z_s[k] * Wn[(size_t)k * Dd + tid];
    g_dup2[((size_t)b * 8 + c) * Dd + tid] = du;
}

// ---------------- fused: u += 0.25*du; optionally v = W[hop] @ u ----------------
__global__ void k_update(const float* __restrict__ W_all, int hop, int do_v) {
    __shared__ float u_s[Dd];
    int b = blockIdx.x, tid = threadIdx.x;
    if (tid < Dd) {
        float s = 0.0f;
#pragma unroll
        for (int c = 0; c < 8; c++) s += g_dup2[((size_t)b * 8 + c) * Dd + tid];
        float nu = g_u[(size_t)b * Dd + tid] + 0.25f * s;
        g_u[(size_t)b * Dd + tid] = nu;
        u_s[tid] = nu;
    }
    __syncthreads();
    if (do_v) {
        const float4* Wr = (const float4*)(W_all + ((size_t)hop * KTOT + tid) * Dd);
        float s = 0.0f;
#pragma unroll 8
        for (int e = 0; e < 32; e++) {
            float4 w = Wr[e];
            float4 uu = *(const float4*)(u_s + e * 4);
            s += w.x * uu.x + w.y * uu.y + w.z * uu.z + w.w * uu.w;
        }
        g_v[(size_t)b * KTOT + tid] = s;
    }
}

// ---------------- init / outputs ----------------
__global__ void k_init_u(const float* __restrict__ hidden) {
    int i = blockIdx.x * blockDim.x + threadIdx.x;
    if (i < Bq * Dd) g_u[i] = hidden[i];
}

__global__ void k_final(float* __restrict__ out) {
    int i = blockIdx.x * blockDim.x + threadIdx.x;
    if (i < ROWS) {
        float l = g_logits[i];
        out[i] = 1.0f / (1.0f + expf(-l));
        out[ROWS + Bq * Dd + i] = l;
    }
    if (i < Bq * Dd) out[ROWS + i] = g_u[i];
}

// ---------------- launch: dual-stream fork/join for overlap ----------------
extern "C" void kernel_launch(void* const* d_in, const int* in_sizes, int n_in,
                              void* d_out, int out_size) {
    const int*   story  = (const int*)d_in[0];
    const int*   kb     = (const int*)d_in[1];
    const int*   cv     = (const int*)d_in[2];
    const float* hidden = (const float*)d_in[3];
    const float* dh     = (const float*)d_in[4];
    const float* adj    = (const float*)d_in[5];
    const float* emb    = (const float*)d_in[6];
    const float* W      = (const float*)d_in[7];
    const float* a      = (const float*)d_in[8];
    float* out = (float*)d_out;

    // persistent side stream + events (created once on first, uncaptured call;
    // must outlive graph capture, so never destroyed here)
    static cudaStream_t s1 = nullptr;
    static cudaEvent_t eF, eS1, eA1, eA2, eA3, eC1, eJ;
    if (s1 == nullptr) {
        cudaStreamCreateWithFlags(&s1, cudaStreamNonBlocking);
        cudaEventCreateWithFlags(&eF,  cudaEventDisableTiming);
        cudaEventCreateWithFlags(&eS1, cudaEventDisableTiming);
        cudaEventCreateWithFlags(&eA1, cudaEventDisableTiming);
        cudaEventCreateWithFlags(&eA2, cudaEventDisableTiming);
        cudaEventCreateWithFlags(&eA3, cudaEventDisableTiming);
        cudaEventCreateWithFlags(&eC1, cudaEventDisableTiming);
        cudaEventCreateWithFlags(&eJ,  cudaEventDisableTiming);
    }

    // fork side stream from the (captured) default stream
    cudaEventRecord(eF, 0);
    cudaStreamWaitEvent(s1, eF, 0);

    // S0: proj -> embed (embed needs wa1/wa2)
    k_proj<<<16, 128>>>(W, a);
    k_embed_f<<<dim3(2048, NHOP), 256>>>(story, kb, cv, dh, emb);
    // S1 (concurrent): neighbor list, u init, v0
    k_build_nbr<<<2048, 256, 0, s1>>>(adj, kb, cv);
    k_init_u<<<8, 256, 0, s1>>>(hidden);
    k_vproj0<<<Bq, 512, 0, s1>>>(W, hidden);
    cudaEventRecord(eS1, s1);

    // S0: attention chain
    cudaStreamWaitEvent(0, eS1, 0);
    k_attn_agg<<<2048, 256>>>(0, 0, 0);            // logits0 fused, no Y store
    k_attn_agg<<<2048, 256>>>(1, 1, 0);            // Y -> buf0
    cudaEventRecord(eA1, 0);
    k_attn_agg<<<2048, 256>>>(2, 1, 1);            // Y -> buf1
    cudaEventRecord(eA2, 0);

    // S1: hop-1 recurrence (reads buf0 + logits0), concurrent with attn(2)
    cudaStreamWaitEvent(s1, eA1, 0);
    k_zpass<<<dim3(Bq, 8), 256, 0, s1>>>(0);
    k_du2<<<dim3(Bq, 8), 128, 0, s1>>>(W, 0);      // W[1]
    k_update<<<Bq, 512, 0, s1>>>(W, 1, 1);         // u1; v1
    k_logits2<<<2048, 256, 0, s1>>>(0);            // logits1 from buf0
    cudaEventRecord(eC1, s1);

    // S0: attn(3) overwrites buf0 -> must wait hop-1 chain (WAR)
    cudaStreamWaitEvent(0, eC1, 0);
    k_attn_agg<<<2048, 256>>>(3, 1, 0);            // Y -> buf0
    cudaEventRecord(eA3, 0);

    // S1: hop-2 recurrence (buf1 + logits1), concurrent with attn(3)
    cudaStreamWaitEvent(s1, eA2, 0);
    k_zpass<<<dim3(Bq, 8), 256, 0, s1>>>(1);
    k_du2<<<dim3(Bq, 8), 128, 0, s1>>>(W, 1);      // W[2]
    k_update<<<Bq, 512, 0, s1>>>(W, 2, 1);         // u2; v2
    k_logits2<<<2048, 256, 0, s1>>>(1);            // logits2 from buf1

    // S1: hop-3 recurrence (buf0 + logits2) + final
    cudaStreamWaitEvent(s1, eA3, 0);
    k_zpass<<<dim3(Bq, 8), 256, 0, s1>>>(0);
    k_du2<<<dim3(Bq, 8), 128, 0, s1>>>(W, 2);      // W[3]
    k_update<<<Bq, 512, 0, s1>>>(W, 3, 0);         // u3 (no v)
    k_final<<<(ROWS + 255) / 256, 256, 0, s1>>>(out);
    cudaEventRecord(eJ, s1);

    // join back to default stream
    cudaStreamWaitEvent(0, eJ, 0);
}

// round 17
// speedup vs baseline: 1.1469x; 1.0036x over previous
#include <cuda_runtime.h>
#include <math.h>

#define Bq     16
#define Nn     1024
#define Dd     128
#define VOCABq 32000
#define HOPSq  3
#define HEADSq 4
#define KMAX   128
#define ALPHAq 0.2f
#define ROWS   (Bq * Nn)   // 16384
#define KTOT   512
#define NHOP   (HOPSq + 1)

// ---------------- device scratch ----------------
__device__ int   g_nbr_idx[ROWS * KMAX];
__device__ int   g_nbr_cnt[ROWS];
__device__ float g_X4[NHOP * ROWS * Dd];
__device__ float g_wa1[16 * Dd];
__device__ float g_wa2[16 * Dd];
__device__ float g_f1p[NHOP * ROWS * 4];
__device__ float g_f2p[NHOP * ROWS * 4];
__device__ float g_Y[(size_t)ROWS * KTOT];      // buffer 0
__device__ float g_Y2[(size_t)ROWS * KTOT];     // buffer 1
__device__ float g_v[Bq * KTOT];
__device__ float g_zpart[Bq * 8 * KTOT];
__device__ float g_dup2[Bq * 8 * Dd];
__device__ float g_u[Bq * Dd];
__device__ float g_logits[ROWS];

// ---------------- neighbor list (pipelined float4 + warp scan) ----------------
__global__ void k_build_nbr(const float* __restrict__ adj,
                            const int* __restrict__ kb_len,
                            const int* __restrict__ conv_len) {
    int warp = (blockIdx.x * blockDim.x + threadIdx.x) >> 5;
    int lane = threadIdx.x & 31;
    if (warp >= ROWS) return;
    int b = warp / Nn, n = warp % Nn;
    int ctx = kb_len[b] + conv_len[b];
    const float* arow = adj + (size_t)warp * Nn;
    int* idx = g_nbr_idx + (size_t)warp * KMAX;
    int cnt = 0;
    bool self_ok = (n >= ctx);

    float4 cur = *(const float4*)(arow + lane * 4);
    for (int m0 = 0; m0 < Nn; m0 += 128) {
        float4 nxt;
        if (m0 + 128 < Nn) nxt = *(const float4*)(arow + m0 + 128 + lane * 4);
        int mb = m0 + lane * 4;
        bool s0 = (cur.x > 0.0f) || (self_ok && mb == n);
        bool s1 = (cur.y > 0.0f) || (self_ok && mb + 1 == n);
        bool s2 = (cur.z > 0.0f) || (self_ok && mb + 2 == n);
        bool s3 = (cur.w > 0.0f) || (self_ok && mb + 3 == n);
        int loc = (int)s0 + (int)s1 + (int)s2 + (int)s3;
        int sc = loc;
#pragma unroll
        for (int o = 1; o < 32; o <<= 1) {
            int t = __shfl_up_sync(0xffffffffu, sc, o);
            if (lane >= o) sc += t;
        }
        int w = cnt + sc - loc;
        if (s0) { if (w < KMAX) idx[w] = mb;     w++; }
        if (s1) { if (w < KMAX) idx[w] = mb + 1; w++; }
        if (s2) { if (w < KMAX) idx[w] = mb + 2; w++; }
        if (s3) { if (w < KMAX) idx[w] = mb + 3; w++; }
        cnt += __shfl_sync(0xffffffffu, sc, 31);
        cur = nxt;
    }
    if (lane == 0) g_nbr_cnt[warp] = cnt < KMAX ? cnt : KMAX;
}

// ---------------- wa = W @ a ----------------
__global__ void k_proj(const float* __restrict__ W_all, const float* __restrict__ a_all) {
    int hh = blockIdx.x;
    int d = threadIdx.x;
    const float* Wrow = W_all + ((size_t)hh * Dd + d) * Dd;
    const float* a = a_all + (size_t)hh * 2 * Dd;
    float s1 = 0.f, s2 = 0.f;
#pragma unroll 4
    for (int e = 0; e < Dd; e++) {
        float w = Wrow[e];
        s1 += w * a[e];
        s2 += w * a[Dd + e];
    }
    g_wa1[hh * Dd + d] = s1;
    g_wa2[hh * Dd + d] = s2;
}

// ------- embedding + LM add + fused f1/f2: 2 rows per warp (MLP 8) -------
__global__ void k_embed_f(const int* __restrict__ story,
                          const int* __restrict__ kb_len,
                          const int* __restrict__ conv_len,
                          const float* __restrict__ dh,
                          const float* __restrict__ emb) {
    int hop = blockIdx.y;
    __shared__ float swa1[HEADSq * Dd];
    __shared__ float swa2[HEADSq * Dd];
    for (int t = threadIdx.x; t < HEADSq * Dd; t += blockDim.x) {
        swa1[t] = g_wa1[hop * HEADSq * Dd + t];
        swa2[t] = g_wa2[hop * HEADSq * Dd + t];
    }
    __syncthreads();
    int warp = (blockIdx.x * blockDim.x + threadIdx.x) >> 5;
    int lane = threadIdx.x & 31;
    int row0 = warp * 2;
    if (row0 >= ROWS) return;
    const float* E = emb + (size_t)hop * VOCABq * Dd;
    int d = lane * 4;

#pragma unroll
    for (int rr = 0; rr < 2; rr++) {
        int row = row0 + rr;
        int b = row / Nn, n = row % Nn;
        const int* st = story + (size_t)row * 4;
        int i0 = st[0], i1 = st[1], i2 = st[2], i3 = st[3];
        float4 v0 = *(const float4*)(E + (size_t)i0 * Dd + d);
        float4 v1 = *(const float4*)(E + (size_t)i1 * Dd + d);
        float4 v2 = *(const float4*)(E + (size_t)i2 * Dd + d);
        float4 v3 = *(const float4*)(E + (size_t)i3 * Dd + d);
        float4 s;
        s.x = v0.x + v1.x + v2.x + v3.x;
        s.y = v0.y + v1.y + v2.y + v3.y;
        s.z = v0.z + v1.z + v2.z + v3.z;
        s.w = v0.w + v1.w + v2.w + v3.w;
        int rel = n - (kb_len[b] - 1);
        if (rel >= 0 && rel < conv_len[b]) {
            float4 g = *(const float4*)(dh + ((size_t)b * Nn + rel) * Dd + d);
            s.x += g.x; s.y += g.y; s.z += g.z; s.w += g.w;
        }
        *(float4*)(g_X4 + ((size_t)hop * ROWS + row) * Dd + d) = s;

        float p1[HEADSq], p2[HEADSq];
#pragma unroll
        for (int h = 0; h < HEADSq; h++) {
            const float* w1 = swa1 + h * Dd + d;
            const float* w2 = swa2 + h * Dd + d;
            p1[h] = s.x * w1[0] + s.y * w1[1] + s.z * w1[2] + s.w * w1[3];
            p2[h] = s.x * w2[0] + s.y * w2[1] + s.z * w2[2] + s.w * w2[3];
        }
#pragma unroll
        for (int o = 16; o; o >>= 1)
#pragma unroll
            for (int h = 0; h < HEADSq; h++) {
                p1[h] += __shfl_xor_sync(0xffffffffu, p1[h], o);
                p2[h] += __shfl_xor_sync(0xffffffffu, p2[h], o);
            }
        if (lane == 0) {
            size_t ro = ((size_t)hop * ROWS + row) * 4;
            *(float4*)(g_f1p + ro) = make_float4(p1[0], p1[1], p1[2], p1[3]);
            *(float4*)(g_f2p + ro) = make_float4(p2[0], p2[1], p2[2], p2[3]);
        }
    }
}

// ---------------- v0 = W[0] @ hidden ----------------
__global__ void k_vproj0(const float* __restrict__ W_all, const float* __restrict__ hidden) {
    int b = blockIdx.x;
    int k = threadIdx.x;
    __shared__ float u_s[Dd];
    if (k < Dd) u_s[k] = hidden[(size_t)b * Dd + k];
    __syncthreads();
    const float4* Wr = (const float4*)(W_all + (size_t)k * Dd);
    float s = 0.0f;
#pragma unroll 8
    for (int e = 0; e < 32; e++) {
        float4 w = Wr[e];
        float4 uu = *(const float4*)(u_s + e * 4);
        s += w.x * uu.x + w.y * uu.y + w.z * uu.z + w.w * uu.w;
    }
    g_v[(size_t)b * KTOT + k] = s;
}

// ------ sparse GAT attention: X -> Y[ybuf]; hop 0 emits logits0 ------
__global__ void k_attn_agg(int hop, int store_y, int ybuf) {
    __shared__ float sw[8][HEADSq][KMAX];
    __shared__ float v_s[KTOT];
    int wl = threadIdx.x >> 5;
    int warp = blockIdx.x * 8 + wl;
    int lane = threadIdx.x & 31;
    int b_blk = (blockIdx.x * 8) / Nn;
    if (hop == 0) {
        for (int t = threadIdx.x; t < KTOT; t += blockDim.x)
            v_s[t] = g_v[(size_t)b_blk * KTOT + t];
        __syncthreads();
    }
    if (warp >= ROWS) return;
    int b = warp / Nn;
    int cnt = g_nbr_cnt[warp];
    const int* idx = g_nbr_idx + (size_t)warp * KMAX;
    int d = lane * 4;
    const float* X = g_X4 + (size_t)hop * ROWS * Dd;
    const float* F2 = g_f2p + (size_t)hop * ROWS * 4 + (size_t)b * Nn * 4;
    float4 acc[HEADSq];
#pragma unroll
    for (int h = 0; h < HEADSq; h++) acc[h] = make_float4(0.f, 0.f, 0.f, 0.f);

    if (cnt == 0) {
        float4 a = make_float4(0.f, 0.f, 0.f, 0.f);
        for (int m = 0; m < Nn; m++) {
            float4 v = *(const float4*)(X + ((size_t)b * Nn + m) * Dd + d);
            a.x += v.x; a.y += v.y; a.z += v.z; a.w += v.w;
        }
        float sc = 1.0f / (float)Nn;
        a.x *= sc; a.y *= sc; a.z *= sc; a.w *= sc;
#pragma unroll
        for (int h = 0; h < HEADSq; h++) acc[h] = a;
    } else {
        float4 f1v = *(const float4*)(g_f1p + ((size_t)hop * ROWS + warp) * 4);
        float f1h[HEADSq] = {f1v.x, f1v.y, f1v.z, f1v.w};
        float mx[HEADSq];
#pragma unroll
        for (int h = 0; h < HEADSq; h++) mx[h] = -3.4e38f;
        for (int j = lane; j < cnt; j += 32) {
            int m = idx[j];
            float4 f2v = *(const float4*)(F2 + (size_t)m * 4);
            float vv[HEADSq] = {f1h[0] + f2v.x, f1h[1] + f2v.y,
                                f1h[2] + f2v.z, f1h[3] + f2v.w};
#pragma unroll
            for (int h = 0; h < HEADSq; h++) {
                float v = vv[h];
                v = (v >= 0.0f) ? v : ALPHAq * v;
                sw[wl][h][j] = v;
                mx[h] = fmaxf(mx[h], v);
            }
        }
#pragma unroll
        for (int o = 16; o; o >>= 1)
#pragma unroll
            for (int h = 0; h < HEADSq; h++)
                mx[h] = fmaxf(mx[h], __shfl_xor_sync(0xffffffffu, mx[h], o));
        __syncwarp();
        float sum[HEADSq] = {0.f, 0.f, 0.f, 0.f};
        for (int j = lane; j < cnt; j += 32) {
#pragma unroll
            for (int h = 0; h < HEADSq; h++) {
                float w = expf(sw[wl][h][j] - mx[h]);
                sw[wl][h][j] = w;
                sum[h] += w;
            }
        }
#pragma unroll
        for (int o = 16; o; o >>= 1)
#pragma unroll
            for (int h = 0; h < HEADSq; h++)
                sum[h] += __shfl_xor_sync(0xffffffffu, sum[h], o);
        float sc[HEADSq];
#pragma unroll
        for (int h = 0; h < HEADSq; h++) sc[h] = 1.0f / sum[h];
        __syncwarp();

        // gather: unroll x8 (two load quads in flight)
        int j = 0;
        for (; j + 8 <= cnt; j += 8) {
            int m0 = idx[j], m1 = idx[j + 1], m2 = idx[j + 2], m3 = idx[j + 3];
            int m4 = idx[j + 4], m5 = idx[j + 5], m6 = idx[j + 6], m7 = idx[j + 7];
            float4 x0 = *(const float4*)(X + ((size_t)b * Nn + m0) * Dd + d);
            float4 x1 = *(const float4*)(X + ((size_t)b * Nn + m1) * Dd + d);
            float4 x2 = *(const float4*)(X + ((size_t)b * Nn + m2) * Dd + d);
            float4 x3 = *(const float4*)(X + ((size_t)b * Nn + m3) * Dd + d);
            float4 x4 = *(const float4*)(X + ((size_t)b * Nn + m4) * Dd + d);
            float4 x5 = *(const float4*)(X + ((size_t)b * Nn + m5) * Dd + d);
            float4 x6 = *(const float4*)(X + ((size_t)b * Nn + m6) * Dd + d);
            float4 x7 = *(const float4*)(X + ((size_t)b * Nn + m7) * Dd + d);
#pragma unroll
            for (int h = 0; h < HEADSq; h++) {
                float w0 = sw[wl][h][j]     * sc[h];
                float w1 = sw[wl][h][j + 1] * sc[h];
                float w2 = sw[wl][h][j + 2] * sc[h];
                float w3 = sw[wl][h][j + 3] * sc[h];
                float w4 = sw[wl][h][j + 4] * sc[h];
                float w5 = sw[wl][h][j + 5] * sc[h];
                float w6 = sw[wl][h][j + 6] * sc[h];
                float w7 = sw[wl][h][j + 7] * sc[h];
                acc[h].x += w0 * x0.x + w1 * x1.x + w2 * x2.x + w3 * x3.x
                          + w4 * x4.x + w5 * x5.x + w6 * x6.x + w7 * x7.x;
                acc[h].y += w0 * x0.y + w1 * x1.y + w2 * x2.y + w3 * x3.y
                          + w4 * x4.y + w5 * x5.y + w6 * x6.y + w7 * x7.y;
                acc[h].z += w0 * x0.z + w1 * x1.z + w2 * x2.z + w3 * x3.z
                          + w4 * x4.z + w5 * x5.z + w6 * x6.z + w7 * x7.z;
                acc[h].w += w0 * x0.w + w1 * x1.w + w2 * x2.w + w3 * x3.w
                          + w4 * x4.w + w5 * x5.w + w6 * x6.w + w7 * x7.w;
            }
        }
        for (; j + 4 <= cnt; j += 4) {
            int m0 = idx[j], m1 = idx[j + 1], m2 = idx[j + 2], m3 = idx[j + 3];
            float4 x0 = *(const float4*)(X + ((size_t)b * Nn + m0) * Dd + d);
            float4 x1 = *(const float4*)(X + ((size_t)b * Nn + m1) * Dd + d);
            float4 x2 = *(const float4*)(X + ((size_t)b * Nn + m2) * Dd + d);
            float4 x3 = *(const float4*)(X + ((size_t)b * Nn + m3) * Dd + d);
#pragma unroll
            for (int h = 0; h < HEADSq; h++) {
                float w0 = sw[wl][h][j]     * sc[h];
                float w1 = sw[wl][h][j + 1] * sc[h];
                float w2 = sw[wl][h][j + 2] * sc[h];
                float w3 = sw[wl][h][j + 3] * sc[h];
                acc[h].x += w0 * x0.x + w1 * x1.x + w2 * x2.x + w3 * x3.x;
                acc[h].y += w0 * x0.y + w1 * x1.y + w2 * x2.y + w3 * x3.y;
                acc[h].z += w0 * x0.z + w1 * x1.z + w2 * x2.z + w3 * x3.z;
                acc[h].w += w0 * x0.w + w1 * x1.w + w2 * x2.w + w3 * x3.w;
            }
        }
        for (; j < cnt; j++) {
            int m = idx[j];
            float4 xv = *(const float4*)(X + ((size_t)b * Nn + m) * Dd + d);
#pragma unroll
            for (int h = 0; h < HEADSq; h++) {
                float w = sw[wl][h][j] * sc[h];
                acc[h].x += w * xv.x; acc[h].y += w * xv.y;
                acc[h].z += w * xv.z; acc[h].w += w * xv.w;
            }
        }
    }

    if (store_y) {
        float* Yb = ybuf ? g_Y2 : g_Y;
        size_t base = (size_t)warp * KTOT;
#pragma unroll
        for (int h = 0; h < HEADSq; h++)
            *(float4*)(Yb + base + h * Dd + d) = acc[h];
    }

    if (hop == 0) {
        float lp = 0.0f;
#pragma unroll
        for (int h = 0; h < HEADSq; h++) {
            const float* vp = v_s + h * Dd + d;
            lp += acc[h].x * vp[0] + acc[h].y * vp[1] +
                  acc[h].z * vp[2] + acc[h].w * vp[3];
        }
#pragma unroll
        for (int o = 16; o; o >>= 1) lp += __shfl_xor_sync(0xffffffffu, lp, o);
        if (lane == 0) g_logits[warp] = 0.25f * lp;
    }
}

// ---------------- logits[row] = 0.25 * Y[row] . v_b ----------------
__global__ void k_logits2(int ybuf) {
    __shared__ float v_s[KTOT];
    int wl = threadIdx.x >> 5;
    int lane = threadIdx.x & 31;
    int row = blockIdx.x * 8 + wl;
    int b = (blockIdx.x * 8) / Nn;
    for (int t = threadIdx.x; t < KTOT; t += blockDim.x)
        v_s[t] = g_v[(size_t)b * KTOT + t];
    __syncthreads();
    const float* Yb = ybuf ? g_Y2 : g_Y;
    const float* Yr = Yb + (size_t)row * KTOT;
    float s = 0.0f;
#pragma unroll
    for (int q = 0; q < 4; q++) {
        int o = q * Dd + lane * 4;
        float4 y = *(const float4*)(Yr + o);
        float4 v = *(const float4*)(v_s + o);
        s += y.x * v.x + y.y * v.y + y.z * v.z + y.w * v.w;
    }
#pragma unroll
    for (int o = 16; o; o >>= 1) s += __shfl_xor_sync(0xffffffffu, s, o);
    if (lane == 0) g_logits[row] = 0.25f * s;
}

// ---------------- z partials ----------------
__global__ void k_zpass(int ybuf) {
    __shared__ float red[256];
    __shared__ float zw[8][KTOT];
    int b = blockIdx.x, split = blockIdx.y;
    int tid = threadIdx.x, wl = tid >> 5, lane = tid & 31;
    const float* lg = g_logits + (size_t)b * Nn;

    float m = -3.4e38f;
#pragma unroll
    for (int i = 0; i < 4; i++) m = fmaxf(m, lg[tid + i * 256]);
    red[tid] = m; __syncthreads();
    for (int s = 128; s; s >>= 1) { if (tid < s) red[tid] = fmaxf(red[tid], red[tid + s]); __syncthreads(); }
    float mx = red[0]; __syncthreads();
    float sum = 0.0f;
#pragma unroll
    for (int i = 0; i < 4; i++) sum += expf(lg[tid + i * 256] - mx);
    red[tid] = sum; __syncthreads();
    for (int s = 128; s; s >>= 1) { if (tid < s) red[tid] += red[tid + s]; __syncthreads(); }
    float inv = 1.0f / red[0];
    __syncthreads();

    float zr[16];
#pragma unroll
    for (int i = 0; i < 16; i++) zr[i] = 0.0f;
    int r0 = split * 128 + wl * 16;
    const float* Ybase = (ybuf ? g_Y2 : g_Y) + (size_t)b * Nn * KTOT;
    for (int i = 0; i < 16; i++) {
        int r = r0 + i;
        float p = expf(lg[r] - mx);
        const float* Yr = Ybase + (size_t)r * KTOT;
#pragma unroll
        for (int q = 0; q < 4; q++) {
            float4 y = *(const float4*)(Yr + q * Dd + lane * 4);
            zr[q * 4 + 0] += p * y.x;
            zr[q * 4 + 1] += p * y.y;
            zr[q * 4 + 2] += p * y.z;
            zr[q * 4 + 3] += p * y.w;
        }
    }
#pragma unroll
    for (int q = 0; q < 4; q++)
        *(float4*)(&zw[wl][q * Dd + lane * 4]) =
            make_float4(zr[q * 4], zr[q * 4 + 1], zr[q * 4 + 2], zr[q * 4 + 3]);
    __syncthreads();
#pragma unroll
    for (int rep = 0; rep < 2; rep++) {
        int c = tid + rep * 256;
        float s = 0.0f;
#pragma unroll
        for (int w = 0; w < 8; w++) s += zw[w][c];
        g_zpart[((size_t)b * 8 + split) * KTOT + c] = s * inv;
    }
}

// ---------------- du partials ----------------
__global__ void k_du2(const float* __restrict__ W_all, int hop) {
    __shared__ float z_s[64];
    int b = blockIdx.x, c = blockIdx.y, tid = threadIdx.x;
    if (tid < 64) {
        int k = c * 64 + tid;
        float s = 0.0f;
#pragma unroll
        for (int s8 = 0; s8 < 8; s8++)
            s += g_zpart[((size_t)b * 8 + s8) * KTOT + k];
        z_s[tid] = s;
    }
    __syncthreads();
    const float* Wn = W_all + ((size_t)(hop + 1) * KTOT + (size_t)c * 64) * Dd;
    float du = 0.0f;
#pragma unroll 8
    for (int k = 0; k < 64; k++) du += z_s[k] * Wn[(size_t)k * Dd + tid];
    g_dup2[((size_t)b * 8 + c) * Dd + tid] = du;
}

// ---------------- fused u update + optional v ----------------
__global__ void k_update(const float* __restrict__ W_all, int hop, int do_v) {
    __shared__ float u_s[Dd];
    int b = blockIdx.x, tid = threadIdx.x;
    if (tid < Dd) {
        float s = 0.0f;
#pragma unroll
        for (int c = 0; c < 8; c++) s += g_dup2[((size_t)b * 8 + c) * Dd + tid];
        float nu = g_u[(size_t)b * Dd + tid] + 0.25f * s;
        g_u[(size_t)b * Dd + tid] = nu;
        u_s[tid] = nu;
    }
    __syncthreads();
    if (do_v) {
        const float4* Wr = (const float4*)(W_all + ((size_t)hop * KTOT + tid) * Dd);
        float s = 0.0f;
#pragma unroll 8
        for (int e = 0; e < 32; e++) {
            float4 w = Wr[e];
            float4 uu = *(const float4*)(u_s + e * 4);
            s += w.x * uu.x + w.y * uu.y + w.z * uu.z + w.w * uu.w;
        }
        g_v[(size_t)b * KTOT + tid] = s;
    }
}

// ---------------- init / outputs ----------------
__global__ void k_init_u(const float* __restrict__ hidden) {
    int i = blockIdx.x * blockDim.x + threadIdx.x;
    if (i < Bq * Dd) g_u[i] = hidden[i];
}

__global__ void k_final(float* __restrict__ out) {
    int i = blockIdx.x * blockDim.x + threadIdx.x;
    if (i < ROWS) {
        float l = g_logits[i];
        out[i] = 1.0f / (1.0f + expf(-l));
        out[ROWS + Bq * Dd + i] = l;
    }
    if (i < Bq * Dd) out[ROWS + i] = g_u[i];
}

// ---------------- launch: dual-stream fork/join ----------------
extern "C" void kernel_launch(void* const* d_in, const int* in_sizes, int n_in,
                              void* d_out, int out_size) {
    const int*   story  = (const int*)d_in[0];
    const int*   kb     = (const int*)d_in[1];
    const int*   cv     = (const int*)d_in[2];
    const float* hidden = (const float*)d_in[3];
    const float* dh     = (const float*)d_in[4];
    const float* adj    = (const float*)d_in[5];
    const float* emb    = (const float*)d_in[6];
    const float* W      = (const float*)d_in[7];
    const float* a      = (const float*)d_in[8];
    float* out = (float*)d_out;

    static cudaStream_t s1 = nullptr;
    static cudaEvent_t eF, eS1, eA1, eA2, eA3, eC1, eJ;
    if (s1 == nullptr) {
        cudaStreamCreateWithFlags(&s1, cudaStreamNonBlocking);
        cudaEventCreateWithFlags(&eF,  cudaEventDisableTiming);
        cudaEventCreateWithFlags(&eS1, cudaEventDisableTiming);
        cudaEventCreateWithFlags(&eA1, cudaEventDisableTiming);
        cudaEventCreateWithFlags(&eA2, cudaEventDisableTiming);
        cudaEventCreateWithFlags(&eA3, cudaEventDisableTiming);
        cudaEventCreateWithFlags(&eC1, cudaEventDisableTiming);
        cudaEventCreateWithFlags(&eJ,  cudaEventDisableTiming);
    }

    cudaEventRecord(eF, 0);
    cudaStreamWaitEvent(s1, eF, 0);

    k_proj<<<16, 128>>>(W, a);
    k_embed_f<<<dim3(1024, NHOP), 256>>>(story, kb, cv, dh, emb);
    k_build_nbr<<<2048, 256, 0, s1>>>(adj, kb, cv);
    k_init_u<<<8, 256, 0, s1>>>(hidden);
    k_vproj0<<<Bq, 512, 0, s1>>>(W, hidden);
    cudaEventRecord(eS1, s1);

    cudaStreamWaitEvent(0, eS1, 0);
    k_attn_agg<<<2048, 256>>>(0, 0, 0);
    k_attn_agg<<<2048, 256>>>(1, 1, 0);
    cudaEventRecord(eA1, 0);
    k_attn_agg<<<2048, 256>>>(2, 1, 1);
    cudaEventRecord(eA2, 0);

    cudaStreamWaitEvent(s1, eA1, 0);
    k_zpass<<<dim3(Bq, 8), 256, 0, s1>>>(0);
    k_du2<<<dim3(Bq, 8), 128, 0, s1>>>(W, 0);
    k_update<<<Bq, 512, 0, s1>>>(W, 1, 1);
    k_logits2<<<2048, 256, 0, s1>>>(0);
    cudaEventRecord(eC1, s1);

    cudaStreamWaitEvent(0, eC1, 0);
    k_attn_agg<<<2048, 256>>>(3, 1, 0);
    cudaEventRecord(eA3, 0);

    cudaStreamWaitEvent(s1, eA2, 0);
    k_zpass<<<dim3(Bq, 8), 256, 0, s1>>>(1);
    k_du2<<<dim3(Bq, 8), 128, 0, s1>>>(W, 1);
    k_update<<<Bq, 512, 0, s1>>>(W, 2, 1);
    k_logits2<<<2048, 256, 0, s1>>>(1);

    cudaStreamWaitEvent(s1, eA3, 0);
    k_zpass<<<dim3(Bq, 8), 256, 0, s1>>>(0);
    k_du2<<<dim3(Bq, 8), 128, 0, s1>>>(W, 2);
    k_update<<<Bq, 512, 0, s1>>>(W, 3, 0);
    k_final<<<(ROWS + 255) / 256, 256, 0, s1>>>(out);
    cudaEventRecord(eJ, s1);

    cudaStreamWaitEvent(0, eJ, 0);
}